// round 15
// baseline (speedup 1.0000x reference)
#include <cuda_runtime.h>
#include <cuda_fp16.h>
#include <cstdint>

typedef unsigned long long u64;
typedef unsigned int u32;
typedef unsigned short u16;

#define NUM_CITIES 50000
#define EMB 50
#define HID 64
#define G4 256          // 4 * HID
#define BATCH 1024
#define SEQ 512
#define K3_CTAS 391     // ceil(50000/128)
#define HSTRIDE 72      // fp16 h row stride (halfs)

// Scratch (no allocation allowed -> device globals)
// layout: g_emb_proj[row][u*4 + G]  (gate-interleaved: G: 0=i 1=f 2=g 3=o)
__device__ float  g_emb_proj[NUM_CITIES * G4];
__device__ __half g_hfin_h[BATCH * HID];          // final hidden state (fp16)
__device__ float  g_partial[K3_CTAS * BATCH];     // per-CTA row partial sums
__device__ float  g_rowinv[BATCH];                // 1/rowsum

// ---------------------------------------------------------------------------
// helpers
// ---------------------------------------------------------------------------
__device__ __forceinline__ float fast_ex2(float x) {
    float r; asm("ex2.approx.f32 %0, %1;" : "=f"(r) : "f"(x)); return r;
}
__device__ __forceinline__ u32 h2tanh(u32 v) {            // 2 tanh per MUFU op
    u32 r; asm("tanh.approx.f16x2 %0, %1;" : "=r"(r) : "r"(v)); return r;
}
__device__ __forceinline__ u32 pack_h2(float a, float b) {
    half2 h = __floats2half2_rn(a, b);
    return *reinterpret_cast<u32*>(&h);
}
__device__ __forceinline__ void unpack2(u64 v, float& lo, float& hi) {
    asm("mov.b64 {%0,%1}, %2;" : "=f"(lo), "=f"(hi) : "l"(v));
}
__device__ __forceinline__ u64 pack2(float lo, float hi) {
    u64 v; asm("mov.b64 %0, {%1,%2};" : "=l"(v) : "f"(lo), "f"(hi)); return v;
}
__device__ __forceinline__ void fma2(u64& acc, u64 a, u64 b) {
    asm("fma.rn.f32x2 %0, %1, %2, %0;" : "+l"(acc) : "l"(a), "l"(b));
}
__device__ __forceinline__ void hmma16816(
    float& d0, float& d1, float& d2, float& d3,
    u32 a0, u32 a1, u32 a2, u32 a3, u32 b0, u32 b1)
{
    asm("mma.sync.aligned.m16n8k16.row.col.f32.f16.f16.f32 "
        "{%0,%1,%2,%3}, {%4,%5,%6,%7}, {%8,%9}, {%0,%1,%2,%3};"
        : "+f"(d0), "+f"(d1), "+f"(d2), "+f"(d3)
        : "r"(a0), "r"(a1), "r"(a2), "r"(a3), "r"(b0), "r"(b1));
}
__device__ __forceinline__ u32 w_half2(const float* __restrict__ W, int j, int k) {
    float2 f = *reinterpret_cast<const float2*>(W + j * HID + k);
    half2 h = __float22half2_rn(f);
    return *reinterpret_cast<u32*>(&h);
}

// no-op launch-slot shifter (puts ncu's fixed sample index on k2)
__global__ void k_nop() {}

// ---------------------------------------------------------------------------
// K1: emb_proj[r][u*4+G] = emb[r]·W_ih[64G+u] + bias(64G+u)
// ---------------------------------------------------------------------------
__global__ void __launch_bounds__(256) k1_embproj(
    const float* __restrict__ emb, const float* __restrict__ W_ih,
    const float* __restrict__ b_ih, const float* __restrict__ b_hh)
{
    __shared__ __align__(16) float es[80][52];
    const int j   = threadIdx.x;
    const int row = 64 * (j & 3) + (j >> 2);     // gate-interleaved mapping
    const int r0  = blockIdx.x * 80;

    u64 wk[26];
    {
        const float2* wr = reinterpret_cast<const float2*>(W_ih + row * 50);
#pragma unroll
        for (int m = 0; m < 25; m++) {
            float2 t = __ldg(&wr[m]);
            wk[m] = pack2(t.x, t.y);
        }
        wk[25] = 0ull;
    }
    const u64 biasp = pack2(b_ih[row] + b_hh[row], 0.0f);

    for (int idx = j; idx < 80 * 50; idx += 256)
        es[idx / 50][idx % 50] = emb[(r0 + idx / 50) * 50 + (idx % 50)];
    if (j < 160) es[j >> 1][50 + (j & 1)] = 0.0f;
    __syncthreads();

#pragma unroll 4
    for (int r = 0; r < 80; r++) {
        u64 acc = biasp;
#pragma unroll
        for (int m = 0; m < 13; m++) {
            ulonglong2 e2 = *reinterpret_cast<const ulonglong2*>(&es[r][m * 4]);
            fma2(acc, e2.x, wk[2 * m]);
            fma2(acc, e2.y, wk[2 * m + 1]);
        }
        float lo, hi; unpack2(acc, lo, hi);
        g_emb_proj[(r0 + r) * G4 + j] = lo + hi;
    }
}

// ---------------------------------------------------------------------------
// K2: LSTM recurrence — R11 layout at HALF the warps per barrier.
// 128 CTAs x 128 threads (4 warps), 8 batches/CTA, all-real N=8.
// Warp w owns units u in [16w, 16w+16) via 4 gate-paired tiles:
//   tile0 = {i(u),f(u)} u in [16w,16w+8)    tile1 = {i,f} u in [16w+8,16w+16)
//   tile2 = {g(u),o(u)} u in [16w,16w+8)    tile3 = {g,o} u in [16w+8,16w+16)
// 16 HMMA/warp/step (serial-K per tile; 4 independent tile chains).
// Lane (g,t4) gets i,f,g,o for (u0=16w+g, u1=u0+8) x (bA=2t4, bB=bA+1):
// 4 register-local updates, no shfl, no divergence. ONE 4-warp barrier/step.
// ---------------------------------------------------------------------------
__global__ void __launch_bounds__(128, 1) k2_lstm(
    const int* __restrict__ x, const float* __restrict__ W_hh)
{
    __shared__ __align__(16) __half hS[2][8 * HSTRIDE];
    __shared__ u16 tokS[8][SEQ];

    const int tid  = threadIdx.x;
    const int lane = tid & 31;
    const int w    = tid >> 5;          // warp 0..3
    const int g    = lane >> 2;         // 0..7
    const int t4   = lane & 3;          // 0..3
    const int b0   = blockIdx.x * 8;

    const int u0 = 16 * w + g;          // first owned unit
    const int u1 = u0 + 8;              // second owned unit
    const int bA = 2 * t4;
    const int bB = bA + 1;

    // A-fragments: [tile][K][4]; tile row-pairs (lo=row g, hi=row g+8):
    //  t0: (u0, 64+u0)   t1: (u1, 64+u1)   t2: (128+u0, 192+u0)  t3: (128+u1, 192+u1)
    u32 A[4][4][4];
    {
        const int loR[4] = { u0, u1, 128 + u0, 128 + u1 };
        const int hiR[4] = { 64 + u0, 64 + u1, 192 + u0, 192 + u1 };
#pragma unroll
        for (int tl = 0; tl < 4; tl++) {
#pragma unroll
            for (int K = 0; K < 4; K++) {
                const int c = 16 * K + 2 * t4;
                A[tl][K][0] = w_half2(W_hh, loR[tl], c);
                A[tl][K][1] = w_half2(W_hh, hiR[tl], c);
                A[tl][K][2] = w_half2(W_hh, loR[tl], c + 8);
                A[tl][K][3] = w_half2(W_hh, hiR[tl], c + 8);
            }
        }
    }

    // zero h buffers
    {
        __half* hz = &hS[0][0];
        for (int i = tid; i < 2 * 8 * HSTRIDE; i += 128) hz[i] = __float2half(0.0f);
    }
    // preload all tokens (u16)
    for (int i = tid; i < 8 * SEQ; i += 128) {
        const int b = i >> 9, t = i & (SEQ - 1);
        tokS[b][t] = (u16)__ldg(&x[(b0 + b) * SEQ + t]);
    }

    // gx(0): float4 of (i,f,g,o) biases per (unit, batch)
    float4 gxA0, gxB0, gxA1, gxB1;
    {
        const int tokA = __ldg(&x[(b0 + bA) * SEQ]);
        const int tokB = __ldg(&x[(b0 + bB) * SEQ]);
        gxA0 = *reinterpret_cast<const float4*>(g_emb_proj + (size_t)tokA * G4 + u0 * 4);
        gxB0 = *reinterpret_cast<const float4*>(g_emb_proj + (size_t)tokB * G4 + u0 * 4);
        gxA1 = *reinterpret_cast<const float4*>(g_emb_proj + (size_t)tokA * G4 + u1 * 4);
        gxB1 = *reinterpret_cast<const float4*>(g_emb_proj + (size_t)tokB * G4 + u1 * 4);
    }

    float cA0 = 0.f, cB0 = 0.f, cA1 = 0.f, cB1 = 0.f;
    float hA0 = 0.f, hB0 = 0.f, hA1 = 0.f, hB1 = 0.f;

    __syncthreads();

    for (int t = 0; t < SEQ; t++) {
        const int buf = t & 1;
        const __half* hb = hS[buf];

        // ---- gx prefetch for t+1 (L2-resident; issued first for overlap) ----
        const int tn = (t + 1 < SEQ) ? (t + 1) : (SEQ - 1);
        const int tokA = tokS[bA][tn];
        const int tokB = tokS[bB][tn];
        float4 nA0 = *reinterpret_cast<const float4*>(g_emb_proj + (size_t)tokA * G4 + u0 * 4);
        float4 nB0 = *reinterpret_cast<const float4*>(g_emb_proj + (size_t)tokB * G4 + u0 * 4);
        float4 nA1 = *reinterpret_cast<const float4*>(g_emb_proj + (size_t)tokA * G4 + u1 * 4);
        float4 nB1 = *reinterpret_cast<const float4*>(g_emb_proj + (size_t)tokB * G4 + u1 * 4);

        // ---- 16 HMMA: 4 tiles x 4 serial K-steps (tiles are independent) ----
        float D[4][4];
#pragma unroll
        for (int tl = 0; tl < 4; tl++) {
            D[tl][0] = 0.f; D[tl][1] = 0.f; D[tl][2] = 0.f; D[tl][3] = 0.f;
        }
#pragma unroll
        for (int K = 0; K < 4; K++) {
            const int kk = 16 * K + 2 * t4;
            u32 bb0 = *reinterpret_cast<const u32*>(&hb[g * HSTRIDE + kk]);
            u32 bb1 = *reinterpret_cast<const u32*>(&hb[g * HSTRIDE + kk + 8]);
#pragma unroll
            for (int tl = 0; tl < 4; tl++)
                hmma16816(D[tl][0], D[tl][1], D[tl][2], D[tl][3],
                          A[tl][K][0], A[tl][K][1], A[tl][K][2], A[tl][K][3], bb0, bb1);
        }

        // ---- epilogue: 4 register-local updates per lane ----
        // tile layout: D[t][0]=(lo,bA) D[t][1]=(lo,bB) D[t][2]=(hi,bA) D[t][3]=(hi,bB)
        // u0: i=D0[0/1], f=D0[2/3], g=D2[0/1], o=D2[2/3]
        // u1: i=D1[0/1], f=D1[2/3], g=D3[0/1], o=D3[2/3]
        {
            float xi0A = D[0][0] + gxA0.x, xi0B = D[0][1] + gxB0.x;
            float xf0A = D[0][2] + gxA0.y, xf0B = D[0][3] + gxB0.y;
            float xg0A = D[2][0] + gxA0.z, xg0B = D[2][1] + gxB0.z;
            float xo0A = D[2][2] + gxA0.w, xo0B = D[2][3] + gxB0.w;
            float xi1A = D[1][0] + gxA1.x, xi1B = D[1][1] + gxB1.x;
            float xf1A = D[1][2] + gxA1.y, xf1B = D[1][3] + gxB1.y;
            float xg1A = D[3][0] + gxA1.z, xg1B = D[3][1] + gxB1.z;
            float xo1A = D[3][2] + gxA1.w, xo1B = D[3][3] + gxB1.w;

            u32 ti0 = h2tanh(pack_h2(0.5f * xi0A, 0.5f * xi0B));
            u32 tf0 = h2tanh(pack_h2(0.5f * xf0A, 0.5f * xf0B));
            u32 tg0 = h2tanh(pack_h2(xg0A, xg0B));
            u32 to0 = h2tanh(pack_h2(0.5f * xo0A, 0.5f * xo0B));
            u32 ti1 = h2tanh(pack_h2(0.5f * xi1A, 0.5f * xi1B));
            u32 tf1 = h2tanh(pack_h2(0.5f * xf1A, 0.5f * xf1B));
            u32 tg1 = h2tanh(pack_h2(xg1A, xg1B));
            u32 to1 = h2tanh(pack_h2(0.5f * xo1A, 0.5f * xo1B));

            half2 hi0 = *reinterpret_cast<half2*>(&ti0), hf0 = *reinterpret_cast<half2*>(&tf0);
            half2 hg0 = *reinterpret_cast<half2*>(&tg0), ho0 = *reinterpret_cast<half2*>(&to0);
            half2 hi1 = *reinterpret_cast<half2*>(&ti1), hf1 = *reinterpret_cast<half2*>(&tf1);
            half2 hg1 = *reinterpret_cast<half2*>(&tg1), ho1 = *reinterpret_cast<half2*>(&to1);

            float i0A = fmaf(0.5f, __low2float(hi0), 0.5f), i0B = fmaf(0.5f, __high2float(hi0), 0.5f);
            float f0A = fmaf(0.5f, __low2float(hf0), 0.5f), f0B = fmaf(0.5f, __high2float(hf0), 0.5f);
            float g0A = __low2float(hg0),                   g0B = __high2float(hg0);
            float o0A = fmaf(0.5f, __low2float(ho0), 0.5f), o0B = fmaf(0.5f, __high2float(ho0), 0.5f);
            float i1A = fmaf(0.5f, __low2float(hi1), 0.5f), i1B = fmaf(0.5f, __high2float(hi1), 0.5f);
            float f1A = fmaf(0.5f, __low2float(hf1), 0.5f), f1B = fmaf(0.5f, __high2float(hf1), 0.5f);
            float g1A = __low2float(hg1),                   g1B = __high2float(hg1);
            float o1A = fmaf(0.5f, __low2float(ho1), 0.5f), o1B = fmaf(0.5f, __high2float(ho1), 0.5f);

            cA0 = fmaf(f0A, cA0, i0A * g0A);
            cB0 = fmaf(f0B, cB0, i0B * g0B);
            cA1 = fmaf(f1A, cA1, i1A * g1A);
            cB1 = fmaf(f1B, cB1, i1B * g1B);

            u32 tc0 = h2tanh(pack_h2(cA0, cB0));
            u32 tc1 = h2tanh(pack_h2(cA1, cB1));
            half2 hc0 = *reinterpret_cast<half2*>(&tc0);
            half2 hc1 = *reinterpret_cast<half2*>(&tc1);
            hA0 = o0A * __low2float(hc0);  hB0 = o0B * __high2float(hc0);
            hA1 = o1A * __low2float(hc1);  hB1 = o1B * __high2float(hc1);
        }

        // publish h(t+1)
        {
            __half* hn = hS[buf ^ 1];
            hn[bA * HSTRIDE + u0] = __float2half(hA0);
            hn[bB * HSTRIDE + u0] = __float2half(hB0);
            hn[bA * HSTRIDE + u1] = __float2half(hA1);
            hn[bB * HSTRIDE + u1] = __float2half(hB1);
        }
        gxA0 = nA0; gxB0 = nB0; gxA1 = nA1; gxB1 = nB1;

        __syncthreads();
    }

    g_hfin_h[(b0 + bA) * HID + u0] = __float2half(hA0);
    g_hfin_h[(b0 + bB) * HID + u0] = __float2half(hB0);
    g_hfin_h[(b0 + bA) * HID + u1] = __float2half(hA1);
    g_hfin_h[(b0 + bB) * HID + u1] = __float2half(hB1);
}

// ---------------------------------------------------------------------------
// K3: tensor-core FC, two-pass, chunk-split over grid.y (4 chunks per CTA).
// store=0: exp row-sums -> g_partial.  store=1: recompute, scale, store.
// ---------------------------------------------------------------------------
__global__ void __launch_bounds__(256) k3_fc(
    const float* __restrict__ W_fc, const float* __restrict__ b_fc,
    float* __restrict__ out, int store)
{
    __shared__ __align__(16) __half hs[64 * HSTRIDE];
    __shared__ float ws[8][64];
    __shared__ float riS[64];

    const int tid  = threadIdx.x;
    const int lane = tid & 31;
    const int w    = tid >> 5;
    const int g    = lane >> 2;
    const int t4   = lane & 3;

    const int cb   = blockIdx.x * 128;
    const int j1   = cb + 16 * w + g;
    const int j2   = j1 + 8;
    const bool v1  = (j1 < NUM_CITIES);
    const bool v2  = (j2 < NUM_CITIES);

    u32 A[4][4];
#pragma unroll
    for (int K = 0; K < 4; K++) {
        const int c = 16 * K + 2 * t4;
        A[K][0] = v1 ? w_half2(W_fc, j1, c)     : 0u;
        A[K][1] = v2 ? w_half2(W_fc, j2, c)     : 0u;
        A[K][2] = v1 ? w_half2(W_fc, j1, c + 8) : 0u;
        A[K][3] = v2 ? w_half2(W_fc, j2, c + 8) : 0u;
    }
    const float bias1 = v1 ? __ldg(&b_fc[j1]) : 0.0f;
    const float bias2 = v2 ? __ldg(&b_fc[j2]) : 0.0f;

    const u32* hsrc = reinterpret_cast<const u32*>(g_hfin_h);
    const int c0 = blockIdx.y * 4;       // 4 chunks per CTA

    for (int chunk = c0; chunk < c0 + 4; chunk++) {
        const int cb64 = chunk * 64;
        __syncthreads();
        for (int i = tid; i < 64 * 32; i += 256) {
            const int r = i >> 5;
            const int cp = i & 31;
            *reinterpret_cast<u32*>(&hs[r * HSTRIDE + 2 * cp]) =
                __ldg(&hsrc[(cb64 + r) * 32 + cp]);
        }
        if (store && tid < 64) riS[tid] = g_rowinv[cb64 + tid];
        __syncthreads();

#pragma unroll
        for (int nt = 0; nt < 8; nt++) {
            const int nb = cb64 + nt * 8;
            float d0 = 0.f, d1 = 0.f, d2 = 0.f, d3 = 0.f;
#pragma unroll
            for (int K = 0; K < 4; K++) {
                const int kk = 16 * K + 2 * t4;
                const __half* hrow = &hs[(nt * 8 + g) * HSTRIDE];
                u32 bb0 = *reinterpret_cast<const u32*>(&hrow[kk]);
                u32 bb1 = *reinterpret_cast<const u32*>(&hrow[kk + 8]);
                hmma16816(d0, d1, d2, d3, A[K][0], A[K][1], A[K][2], A[K][3], bb0, bb1);
            }
            const float LOG2E = 1.4426950408889634f;
            float e0 = v1 ? fast_ex2((d0 + bias1) * LOG2E) : 0.0f;
            float e1 = v1 ? fast_ex2((d1 + bias1) * LOG2E) : 0.0f;
            float e2 = v2 ? fast_ex2((d2 + bias2) * LOG2E) : 0.0f;
            float e3 = v2 ? fast_ex2((d3 + bias2) * LOG2E) : 0.0f;

            if (store) {
                const float r0v = riS[(nt * 8 + 2 * t4) & 63];
                const float r1v = riS[(nt * 8 + 2 * t4 + 1) & 63];
                const size_t rA = (size_t)(nb + 2 * t4) * NUM_CITIES;
                const size_t rB = (size_t)(nb + 2 * t4 + 1) * NUM_CITIES;
                if (v1) { __stcs(&out[rA + j1], e0 * r0v); __stcs(&out[rB + j1], e1 * r1v); }
                if (v2) { __stcs(&out[rA + j2], e2 * r0v); __stcs(&out[rB + j2], e3 * r1v); }
            } else {
                float s0 = e0 + e2;
                float s1 = e1 + e3;
#pragma unroll
                for (int m = 4; m <= 16; m <<= 1) {
                    s0 += __shfl_xor_sync(0xffffffffu, s0, m);
                    s1 += __shfl_xor_sync(0xffffffffu, s1, m);
                }
                if (g == 0) {
                    ws[w][nt * 8 + 2 * t4]     = s0;
                    ws[w][nt * 8 + 2 * t4 + 1] = s1;
                }
            }
        }
        if (!store) {
            __syncthreads();
            if (tid < 64) {
                float s = 0.0f;
#pragma unroll
                for (int ww = 0; ww < 8; ww++) s += ws[ww][tid];
                g_partial[blockIdx.x * BATCH + cb64 + tid] = s;
            }
        }
    }
}

// ---------------------------------------------------------------------------
// K3c: exact row-sum inverses. One warp per batch row.
// ---------------------------------------------------------------------------
__global__ void __launch_bounds__(128) k3c_inv()
{
    const int warp = (blockIdx.x * 128 + threadIdx.x) >> 5;
    const int lane = threadIdx.x & 31;
    float s = 0.0f;
    for (int cta = lane; cta < K3_CTAS; cta += 32)
        s += g_partial[cta * BATCH + warp];
    s += __shfl_xor_sync(0xffffffffu, s, 16);
    s += __shfl_xor_sync(0xffffffffu, s, 8);
    s += __shfl_xor_sync(0xffffffffu, s, 4);
    s += __shfl_xor_sync(0xffffffffu, s, 2);
    s += __shfl_xor_sync(0xffffffffu, s, 1);
    if (lane == 0) g_rowinv[warp] = 1.0f / s;
}

// ---------------------------------------------------------------------------
extern "C" void kernel_launch(void* const* d_in, const int* in_sizes, int n_in,
                              void* d_out, int out_size)
{
    (void)in_sizes; (void)n_in; (void)out_size;
    const int*   x    = (const int*)  d_in[0];
    const float* emb  = (const float*)d_in[1];
    const float* W_ih = (const float*)d_in[2];
    const float* W_hh = (const float*)d_in[3];
    const float* b_ih = (const float*)d_in[4];
    const float* b_hh = (const float*)d_in[5];
    const float* W_fc = (const float*)d_in[6];
    const float* b_fc = (const float*)d_in[7];
    float* out = (float*)d_out;

    k1_embproj<<<NUM_CITIES / 80, 256>>>(emb, W_ih, b_ih, b_hh);
    k_nop<<<1, 32>>>();
    k_nop<<<1, 32>>>();
    k2_lstm<<<BATCH / 8, 128>>>(x, W_hh);          // launch idx 3 -> profiled
    dim3 g3(K3_CTAS, 4);
    k3_fc<<<g3, 256>>>(W_fc, b_fc, out, 0);
    k3c_inv<<<256, 128>>>();
    k3_fc<<<g3, 256>>>(W_fc, b_fc, out, 1);
}

// round 16
// speedup vs baseline: 1.1201x; 1.1201x over previous
#include <cuda_runtime.h>
#include <cuda_fp16.h>
#include <cstdint>

typedef unsigned long long u64;
typedef unsigned int u32;
typedef unsigned short u16;

#define NUM_CITIES 50000
#define EMB 50
#define HID 64
#define G4 256          // 4 * HID
#define BATCH 1024
#define SEQ 512
#define K3_CTAS 391     // ceil(50000/128)
#define HSTRIDE 72      // fp16 h row stride (halfs)
#define TSP 132         // pass2 transpose tile row stride (floats)

// Scratch (no allocation allowed -> device globals)
// layout: g_emb_proj[row][u*4 + G]  (gate-interleaved: G: 0=i 1=f 2=g 3=o)
__device__ float  g_emb_proj[NUM_CITIES * G4];
__device__ __half g_hfin_h[BATCH * HID];          // final hidden state (fp16)
__device__ float  g_partial[K3_CTAS * BATCH];     // per-CTA row partial sums
__device__ float  g_rowinv[BATCH];                // 1/rowsum

// ---------------------------------------------------------------------------
// helpers
// ---------------------------------------------------------------------------
__device__ __forceinline__ float fast_ex2(float x) {
    float r; asm("ex2.approx.f32 %0, %1;" : "=f"(r) : "f"(x)); return r;
}
__device__ __forceinline__ u32 h2tanh(u32 v) {            // 2 tanh per MUFU op
    u32 r; asm("tanh.approx.f16x2 %0, %1;" : "=r"(r) : "r"(v)); return r;
}
__device__ __forceinline__ u32 pack_h2(float a, float b) {
    half2 h = __floats2half2_rn(a, b);
    return *reinterpret_cast<u32*>(&h);
}
__device__ __forceinline__ void unpack2(u64 v, float& lo, float& hi) {
    asm("mov.b64 {%0,%1}, %2;" : "=f"(lo), "=f"(hi) : "l"(v));
}
__device__ __forceinline__ u64 pack2(float lo, float hi) {
    u64 v; asm("mov.b64 %0, {%1,%2};" : "=l"(v) : "f"(lo), "f"(hi)); return v;
}
__device__ __forceinline__ void fma2(u64& acc, u64 a, u64 b) {
    asm("fma.rn.f32x2 %0, %1, %2, %0;" : "+l"(acc) : "l"(a), "l"(b));
}
__device__ __forceinline__ void hmma16816(
    float& d0, float& d1, float& d2, float& d3,
    u32 a0, u32 a1, u32 a2, u32 a3, u32 b0, u32 b1)
{
    asm("mma.sync.aligned.m16n8k16.row.col.f32.f16.f16.f32 "
        "{%0,%1,%2,%3}, {%4,%5,%6,%7}, {%8,%9}, {%0,%1,%2,%3};"
        : "+f"(d0), "+f"(d1), "+f"(d2), "+f"(d3)
        : "r"(a0), "r"(a1), "r"(a2), "r"(a3), "r"(b0), "r"(b1));
}
__device__ __forceinline__ u32 w_half2(const float* __restrict__ W, int j, int k) {
    float2 f = *reinterpret_cast<const float2*>(W + j * HID + k);
    half2 h = __float22half2_rn(f);
    return *reinterpret_cast<u32*>(&h);
}

// no-op launch-slot shifter (keeps ncu's fixed sample index on k2)
__global__ void k_nop() {}

// ---------------------------------------------------------------------------
// K1: emb_proj[r][u*4+G] = emb[r]·W_ih[64G+u] + bias(64G+u)
// ---------------------------------------------------------------------------
__global__ void __launch_bounds__(256) k1_embproj(
    const float* __restrict__ emb, const float* __restrict__ W_ih,
    const float* __restrict__ b_ih, const float* __restrict__ b_hh)
{
    __shared__ __align__(16) float es[80][52];
    const int j   = threadIdx.x;
    const int row = 64 * (j & 3) + (j >> 2);     // gate-interleaved mapping
    const int r0  = blockIdx.x * 80;

    u64 wk[26];
    {
        const float2* wr = reinterpret_cast<const float2*>(W_ih + row * 50);
#pragma unroll
        for (int m = 0; m < 25; m++) {
            float2 t = __ldg(&wr[m]);
            wk[m] = pack2(t.x, t.y);
        }
        wk[25] = 0ull;
    }
    const u64 biasp = pack2(b_ih[row] + b_hh[row], 0.0f);

    for (int idx = j; idx < 80 * 50; idx += 256)
        es[idx / 50][idx % 50] = emb[(r0 + idx / 50) * 50 + (idx % 50)];
    if (j < 160) es[j >> 1][50 + (j & 1)] = 0.0f;
    __syncthreads();

#pragma unroll 4
    for (int r = 0; r < 80; r++) {
        u64 acc = biasp;
#pragma unroll
        for (int m = 0; m < 13; m++) {
            ulonglong2 e2 = *reinterpret_cast<const ulonglong2*>(&es[r][m * 4]);
            fma2(acc, e2.x, wk[2 * m]);
            fma2(acc, e2.y, wk[2 * m + 1]);
        }
        float lo, hi; unpack2(acc, lo, hi);
        g_emb_proj[(r0 + r) * G4 + j] = lo + hi;
    }
}

// ---------------------------------------------------------------------------
// K2: LSTM recurrence (R11/R14 configuration — measured best at 198us).
// 128 CTAs x 256 threads (8 warps), 8 batches/CTA, all-real N=8.
// Gate-paired tiling: warp w owns units u in [8w, 8w+8):
//   tile0 rows = { i(u), f(u) }, tile1 rows = { g(u), o(u) }.
// 8 HMMA/warp/step, split-K. Lane (g,t4) gets i,f,g,o for
// (u=8w+g, b=2t4 & 2t4+1): register-local update, no shfl. 1 barrier/step.
// ---------------------------------------------------------------------------
__global__ void __launch_bounds__(256, 1) k2_lstm(
    const int* __restrict__ x, const float* __restrict__ W_hh)
{
    __shared__ __align__(16) __half hS[2][8 * HSTRIDE];
    __shared__ u16 tokS[8][SEQ];

    const int tid  = threadIdx.x;
    const int lane = tid & 31;
    const int w    = tid >> 5;          // warp 0..7
    const int g    = lane >> 2;         // 0..7
    const int t4   = lane & 3;          // 0..3
    const int b0   = blockIdx.x * 8;

    const int u  = 8 * w + g;           // hidden unit owned by this lane
    const int bA = 2 * t4;              // lane's two batches
    const int bB = bA + 1;

    // stationary A-fragments. tile0: rows g->i(u), g+8->f(u). tile1: g/o.
    u32 A0[4][4], A1[4][4];
#pragma unroll
    for (int K = 0; K < 4; K++) {
        const int c = 16 * K + 2 * t4;
        A0[K][0] = w_half2(W_hh,       u, c);      // i
        A0[K][1] = w_half2(W_hh,  64 + u, c);      // f
        A0[K][2] = w_half2(W_hh,       u, c + 8);
        A0[K][3] = w_half2(W_hh,  64 + u, c + 8);
        A1[K][0] = w_half2(W_hh, 128 + u, c);      // g
        A1[K][1] = w_half2(W_hh, 192 + u, c);      // o
        A1[K][2] = w_half2(W_hh, 128 + u, c + 8);
        A1[K][3] = w_half2(W_hh, 192 + u, c + 8);
    }

    // zero h buffers
    {
        __half* hz = &hS[0][0];
        for (int i = tid; i < 2 * 8 * HSTRIDE; i += 256) hz[i] = __float2half(0.0f);
    }
    // preload all tokens (u16)
    for (int i = tid; i < 8 * SEQ; i += 256) {
        const int b = i >> 9, t = i & (SEQ - 1);
        tokS[b][t] = (u16)__ldg(&x[(b0 + b) * SEQ + t]);
    }

    // gx(0): one float4 per (u, batch)
    float4 gxA, gxB;
    {
        const int tokA = __ldg(&x[(b0 + bA) * SEQ]);
        const int tokB = __ldg(&x[(b0 + bB) * SEQ]);
        gxA = *reinterpret_cast<const float4*>(g_emb_proj + (size_t)tokA * G4 + u * 4);
        gxB = *reinterpret_cast<const float4*>(g_emb_proj + (size_t)tokB * G4 + u * 4);
    }

    float cA = 0.f, cB = 0.f, hAv = 0.f, hBv = 0.f;

    __syncthreads();

    for (int t = 0; t < SEQ; t++) {
        const int buf = t & 1;
        const __half* hb = hS[buf];

        // ---- gx prefetch for t+1 (L2-resident; issued first for overlap) ----
        const int tn = (t + 1 < SEQ) ? (t + 1) : (SEQ - 1);
        const int tokA = tokS[bA][tn];
        const int tokB = tokS[bB][tn];
        float4 nA = *reinterpret_cast<const float4*>(g_emb_proj + (size_t)tokA * G4 + u * 4);
        float4 nB = *reinterpret_cast<const float4*>(g_emb_proj + (size_t)tokB * G4 + u * 4);

        // ---- 8 HMMA, split-K (K0,K1 -> chain a; K2,K3 -> chain b) ----
        float d0a=0.f,d1a=0.f,d2a=0.f,d3a=0.f, d0b=0.f,d1b=0.f,d2b=0.f,d3b=0.f;
        float e0a=0.f,e1a=0.f,e2a=0.f,e3a=0.f, e0b=0.f,e1b=0.f,e2b=0.f,e3b=0.f;
#pragma unroll
        for (int K = 0; K < 4; K++) {
            const int kk = 16 * K + 2 * t4;
            u32 bb0 = *reinterpret_cast<const u32*>(&hb[g * HSTRIDE + kk]);
            u32 bb1 = *reinterpret_cast<const u32*>(&hb[g * HSTRIDE + kk + 8]);
            if (K < 2) {
                hmma16816(d0a,d1a,d2a,d3a, A0[K][0],A0[K][1],A0[K][2],A0[K][3], bb0,bb1);
                hmma16816(e0a,e1a,e2a,e3a, A1[K][0],A1[K][1],A1[K][2],A1[K][3], bb0,bb1);
            } else {
                hmma16816(d0b,d1b,d2b,d3b, A0[K][0],A0[K][1],A0[K][2],A0[K][3], bb0,bb1);
                hmma16816(e0b,e1b,e2b,e3b, A1[K][0],A1[K][1],A1[K][2],A1[K][3], bb0,bb1);
            }
        }

        // ---- epilogue: all lanes, register-local ----
        float xi0 = d0a + d0b + gxA.x, xi1 = d1a + d1b + gxB.x;
        float xf0 = d2a + d2b + gxA.y, xf1 = d3a + d3b + gxB.y;
        float xg0 = e0a + e0b + gxA.z, xg1 = e1a + e1b + gxB.z;
        float xo0 = e2a + e2b + gxA.w, xo1 = e3a + e3b + gxB.w;

        u32 ti = h2tanh(pack_h2(0.5f * xi0, 0.5f * xi1));
        u32 tf = h2tanh(pack_h2(0.5f * xf0, 0.5f * xf1));
        u32 tg = h2tanh(pack_h2(xg0, xg1));
        u32 to = h2tanh(pack_h2(0.5f * xo0, 0.5f * xo1));
        half2 hti = *reinterpret_cast<half2*>(&ti);
        half2 htf = *reinterpret_cast<half2*>(&tf);
        half2 htg = *reinterpret_cast<half2*>(&tg);
        half2 hto = *reinterpret_cast<half2*>(&to);

        float i0 = fmaf(0.5f, __low2float(hti), 0.5f), i1 = fmaf(0.5f, __high2float(hti), 0.5f);
        float f0 = fmaf(0.5f, __low2float(htf), 0.5f), f1 = fmaf(0.5f, __high2float(htf), 0.5f);
        float g0 = __low2float(htg),                   g1 = __high2float(htg);
        float o0 = fmaf(0.5f, __low2float(hto), 0.5f), o1 = fmaf(0.5f, __high2float(hto), 0.5f);

        cA = fmaf(f0, cA, i0 * g0);
        cB = fmaf(f1, cB, i1 * g1);
        u32 tc = h2tanh(pack_h2(cA, cB));
        half2 htc = *reinterpret_cast<half2*>(&tc);
        hAv = o0 * __low2float(htc);
        hBv = o1 * __high2float(htc);

        // publish h(t+1)
        {
            __half* hn = hS[buf ^ 1];
            hn[bA * HSTRIDE + u] = __float2half(hAv);
            hn[bB * HSTRIDE + u] = __float2half(hBv);
        }
        gxA = nA; gxB = nB;

        __syncthreads();
    }

    g_hfin_h[(b0 + bA) * HID + u] = __float2half(hAv);
    g_hfin_h[(b0 + bB) * HID + u] = __float2half(hBv);
}

// ---------------------------------------------------------------------------
// K3: tensor-core FC, two-pass, chunk-split over grid.y (4 chunks per CTA).
// store=0: exp row-sums -> g_partial.
// store=1: recompute, scale by g_rowinv, stage 64x128 tile in smem,
//          write with fully-coalesced float4 stores.
// ---------------------------------------------------------------------------
__global__ void __launch_bounds__(256) k3_fc(
    const float* __restrict__ W_fc, const float* __restrict__ b_fc,
    float* __restrict__ out, int store)
{
    __shared__ __align__(16) __half hs[64 * HSTRIDE];
    __shared__ float ws[8][64];
    __shared__ float riS[64];
    __shared__ __align__(16) float ts[64 * TSP];   // transpose tile (pass2)

    const int tid  = threadIdx.x;
    const int lane = tid & 31;
    const int w    = tid >> 5;
    const int g    = lane >> 2;
    const int t4   = lane & 3;

    const int cb   = blockIdx.x * 128;
    const int j1   = cb + 16 * w + g;
    const int j2   = j1 + 8;
    const bool v1  = (j1 < NUM_CITIES);
    const bool v2  = (j2 < NUM_CITIES);
    const int c1   = 16 * w + g;        // CTA-local city col
    const int c2   = c1 + 8;

    u32 A[4][4];
#pragma unroll
    for (int K = 0; K < 4; K++) {
        const int c = 16 * K + 2 * t4;
        A[K][0] = v1 ? w_half2(W_fc, j1, c)     : 0u;
        A[K][1] = v2 ? w_half2(W_fc, j2, c)     : 0u;
        A[K][2] = v1 ? w_half2(W_fc, j1, c + 8) : 0u;
        A[K][3] = v2 ? w_half2(W_fc, j2, c + 8) : 0u;
    }
    const float bias1 = v1 ? __ldg(&b_fc[j1]) : 0.0f;
    const float bias2 = v2 ? __ldg(&b_fc[j2]) : 0.0f;

    const u32* hsrc = reinterpret_cast<const u32*>(g_hfin_h);
    const int c0 = blockIdx.y * 4;       // 4 chunks per CTA

    for (int chunk = c0; chunk < c0 + 4; chunk++) {
        const int cb64 = chunk * 64;
        __syncthreads();
        for (int i = tid; i < 64 * 32; i += 256) {
            const int r = i >> 5;
            const int cp = i & 31;
            *reinterpret_cast<u32*>(&hs[r * HSTRIDE + 2 * cp]) =
                __ldg(&hsrc[(cb64 + r) * 32 + cp]);
        }
        if (store && tid < 64) riS[tid] = g_rowinv[cb64 + tid];
        __syncthreads();

#pragma unroll
        for (int nt = 0; nt < 8; nt++) {
            float d0 = 0.f, d1 = 0.f, d2 = 0.f, d3 = 0.f;
#pragma unroll
            for (int K = 0; K < 4; K++) {
                const int kk = 16 * K + 2 * t4;
                const __half* hrow = &hs[(nt * 8 + g) * HSTRIDE];
                u32 bb0 = *reinterpret_cast<const u32*>(&hrow[kk]);
                u32 bb1 = *reinterpret_cast<const u32*>(&hrow[kk + 8]);
                hmma16816(d0, d1, d2, d3, A[K][0], A[K][1], A[K][2], A[K][3], bb0, bb1);
            }
            const float LOG2E = 1.4426950408889634f;
            float e0 = v1 ? fast_ex2((d0 + bias1) * LOG2E) : 0.0f;
            float e1 = v1 ? fast_ex2((d1 + bias1) * LOG2E) : 0.0f;
            float e2 = v2 ? fast_ex2((d2 + bias2) * LOG2E) : 0.0f;
            float e3 = v2 ? fast_ex2((d3 + bias2) * LOG2E) : 0.0f;

            if (store) {
                const int r0i = nt * 8 + 2 * t4;       // chunk-local row
                const float rv0 = riS[r0i];
                const float rv1 = riS[r0i + 1];
                ts[r0i * TSP + c1]       = e0 * rv0;
                ts[(r0i + 1) * TSP + c1] = e1 * rv1;
                ts[r0i * TSP + c2]       = e2 * rv0;
                ts[(r0i + 1) * TSP + c2] = e3 * rv1;
            } else {
                const int nb = cb64 + nt * 8;
                (void)nb;
                float s0 = e0 + e2;
                float s1 = e1 + e3;
#pragma unroll
                for (int m = 4; m <= 16; m <<= 1) {
                    s0 += __shfl_xor_sync(0xffffffffu, s0, m);
                    s1 += __shfl_xor_sync(0xffffffffu, s1, m);
                }
                if (g == 0) {
                    ws[w][nt * 8 + 2 * t4]     = s0;
                    ws[w][nt * 8 + 2 * t4 + 1] = s1;
                }
            }
        }

        if (store) {
            __syncthreads();
            // fully-coalesced float4 stores of the 64 x 128 tile
            for (int i = tid; i < 64 * 32; i += 256) {
                const int r  = i >> 5;
                const int c4 = i & 31;
                if (cb + 4 * c4 + 3 < NUM_CITIES) {
                    float4 v = *reinterpret_cast<const float4*>(&ts[r * TSP + 4 * c4]);
                    __stcs(reinterpret_cast<float4*>(
                        out + (size_t)(cb64 + r) * NUM_CITIES + cb + 4 * c4), v);
                }
            }
        } else {
            __syncthreads();
            if (tid < 64) {
                float s = 0.0f;
#pragma unroll
                for (int ww = 0; ww < 8; ww++) s += ws[ww][tid];
                g_partial[blockIdx.x * BATCH + cb64 + tid] = s;
            }
        }
    }
}

// ---------------------------------------------------------------------------
// K3c: exact row-sum inverses. One warp per batch row.
// ---------------------------------------------------------------------------
__global__ void __launch_bounds__(128) k3c_inv()
{
    const int warp = (blockIdx.x * 128 + threadIdx.x) >> 5;
    const int lane = threadIdx.x & 31;
    float s = 0.0f;
    for (int cta = lane; cta < K3_CTAS; cta += 32)
        s += g_partial[cta * BATCH + warp];
    s += __shfl_xor_sync(0xffffffffu, s, 16);
    s += __shfl_xor_sync(0xffffffffu, s, 8);
    s += __shfl_xor_sync(0xffffffffu, s, 4);
    s += __shfl_xor_sync(0xffffffffu, s, 2);
    s += __shfl_xor_sync(0xffffffffu, s, 1);
    if (lane == 0) g_rowinv[warp] = 1.0f / s;
}

// ---------------------------------------------------------------------------
extern "C" void kernel_launch(void* const* d_in, const int* in_sizes, int n_in,
                              void* d_out, int out_size)
{
    (void)in_sizes; (void)n_in; (void)out_size;
    const int*   x    = (const int*)  d_in[0];
    const float* emb  = (const float*)d_in[1];
    const float* W_ih = (const float*)d_in[2];
    const float* W_hh = (const float*)d_in[3];
    const float* b_ih = (const float*)d_in[4];
    const float* b_hh = (const float*)d_in[5];
    const float* W_fc = (const float*)d_in[6];
    const float* b_fc = (const float*)d_in[7];
    float* out = (float*)d_out;

    k1_embproj<<<NUM_CITIES / 80, 256>>>(emb, W_ih, b_ih, b_hh);
    k_nop<<<1, 32>>>();
    k_nop<<<1, 32>>>();
    k2_lstm<<<BATCH / 8, 256>>>(x, W_hh);          // launch idx 3 -> profiled
    dim3 g3(K3_CTAS, 4);
    k3_fc<<<g3, 256>>>(W_fc, b_fc, out, 0);
    k3c_inv<<<256, 128>>>();
    k3_fc<<<g3, 256>>>(W_fc, b_fc, out, 1);
}

// round 17
// speedup vs baseline: 1.1346x; 1.0130x over previous
#include <cuda_runtime.h>
#include <cuda_fp16.h>
#include <cstdint>

typedef unsigned long long u64;
typedef unsigned int u32;
typedef unsigned short u16;

#define NUM_CITIES 50000
#define EMB 50
#define HID 64
#define G4 256          // 4 * HID
#define BATCH 1024
#define SEQ 512
#define K3_CTAS 391     // ceil(50000/128)
#define HSTRIDE 72      // fp16 h row stride (halfs)

// Scratch (no allocation allowed -> device globals)
// layout: g_emb_proj_h[row][u*4 + G] fp16 (gate-interleaved: 0=i 1=f 2=g 3=o)
__device__ __half g_emb_proj_h[NUM_CITIES * G4];  // 25.6MB, L2-resident
__device__ __half g_hfin_h[BATCH * HID];          // final hidden state (fp16)
__device__ float  g_partial[K3_CTAS * BATCH];     // per-CTA row partial sums
__device__ float  g_rowinv[BATCH];                // 1/rowsum

// ---------------------------------------------------------------------------
// helpers
// ---------------------------------------------------------------------------
__device__ __forceinline__ float fast_ex2(float x) {
    float r; asm("ex2.approx.f32 %0, %1;" : "=f"(r) : "f"(x)); return r;
}
__device__ __forceinline__ u32 h2tanh(u32 v) {            // 2 tanh per MUFU op
    u32 r; asm("tanh.approx.f16x2 %0, %1;" : "=r"(r) : "r"(v)); return r;
}
__device__ __forceinline__ u32 pack_h2(float a, float b) {
    half2 h = __floats2half2_rn(a, b);
    return *reinterpret_cast<u32*>(&h);
}
__device__ __forceinline__ void unpack2(u64 v, float& lo, float& hi) {
    asm("mov.b64 {%0,%1}, %2;" : "=f"(lo), "=f"(hi) : "l"(v));
}
__device__ __forceinline__ u64 pack2(float lo, float hi) {
    u64 v; asm("mov.b64 %0, {%1,%2};" : "=l"(v) : "f"(lo), "f"(hi)); return v;
}
__device__ __forceinline__ void fma2(u64& acc, u64 a, u64 b) {
    asm("fma.rn.f32x2 %0, %1, %2, %0;" : "+l"(acc) : "l"(a), "l"(b));
}
__device__ __forceinline__ void hmma16816(
    float& d0, float& d1, float& d2, float& d3,
    u32 a0, u32 a1, u32 a2, u32 a3, u32 b0, u32 b1)
{
    asm("mma.sync.aligned.m16n8k16.row.col.f32.f16.f16.f32 "
        "{%0,%1,%2,%3}, {%4,%5,%6,%7}, {%8,%9}, {%0,%1,%2,%3};"
        : "+f"(d0), "+f"(d1), "+f"(d2), "+f"(d3)
        : "r"(a0), "r"(a1), "r"(a2), "r"(a3), "r"(b0), "r"(b1));
}
__device__ __forceinline__ u32 w_half2(const float* __restrict__ W, int j, int k) {
    float2 f = *reinterpret_cast<const float2*>(W + j * HID + k);
    half2 h = __float22half2_rn(f);
    return *reinterpret_cast<u32*>(&h);
}
// unpack uint2 of 4 halves (i,f | g,o) into 4 floats
__device__ __forceinline__ void gx4(uint2 p, float& gi, float& gf, float& gg, float& go) {
    half2 a = *reinterpret_cast<half2*>(&p.x);
    half2 b = *reinterpret_cast<half2*>(&p.y);
    float2 fa = __half22float2(a);
    float2 fb = __half22float2(b);
    gi = fa.x; gf = fa.y; gg = fb.x; go = fb.y;
}

// no-op launch-slot shifter (keeps ncu's fixed sample index on k2)
__global__ void k_nop() {}

// ---------------------------------------------------------------------------
// K1: emb_proj_h[r][u*4+G] = fp16( emb[r]·W_ih[64G+u] + bias(64G+u) )
// ---------------------------------------------------------------------------
__global__ void __launch_bounds__(256) k1_embproj(
    const float* __restrict__ emb, const float* __restrict__ W_ih,
    const float* __restrict__ b_ih, const float* __restrict__ b_hh)
{
    __shared__ __align__(16) float es[80][52];
    const int j   = threadIdx.x;
    const int row = 64 * (j & 3) + (j >> 2);     // gate-interleaved mapping
    const int r0  = blockIdx.x * 80;

    u64 wk[26];
    {
        const float2* wr = reinterpret_cast<const float2*>(W_ih + row * 50);
#pragma unroll
        for (int m = 0; m < 25; m++) {
            float2 t = __ldg(&wr[m]);
            wk[m] = pack2(t.x, t.y);
        }
        wk[25] = 0ull;
    }
    const u64 biasp = pack2(b_ih[row] + b_hh[row], 0.0f);

    for (int idx = j; idx < 80 * 50; idx += 256)
        es[idx / 50][idx % 50] = emb[(r0 + idx / 50) * 50 + (idx % 50)];
    if (j < 160) es[j >> 1][50 + (j & 1)] = 0.0f;
    __syncthreads();

#pragma unroll 4
    for (int r = 0; r < 80; r++) {
        u64 acc = biasp;
#pragma unroll
        for (int m = 0; m < 13; m++) {
            ulonglong2 e2 = *reinterpret_cast<const ulonglong2*>(&es[r][m * 4]);
            fma2(acc, e2.x, wk[2 * m]);
            fma2(acc, e2.y, wk[2 * m + 1]);
        }
        float lo, hi; unpack2(acc, lo, hi);
        g_emb_proj_h[(r0 + r) * G4 + j] = __float2half(lo + hi);
    }
}

// ---------------------------------------------------------------------------
// K2: LSTM recurrence (R11/R14 structure, fp16 gx table).
// 128 CTAs x 256 threads (8 warps), 8 batches/CTA, all-real N=8.
// Gate-paired tiling: warp w owns units u in [8w, 8w+8):
//   tile0 rows = { i(u), f(u) }, tile1 rows = { g(u), o(u) }.
// 8 HMMA/warp/step, split-K. Lane (g,t4) gets i,f,g,o for
// (u=8w+g, b=2t4 & 2t4+1): register-local update, no shfl. 1 barrier/step.
// gx fetched as 8B uint2 (fp16 x4) -> half the L1tex wavefronts.
// ---------------------------------------------------------------------------
__global__ void __launch_bounds__(256, 1) k2_lstm(
    const int* __restrict__ x, const float* __restrict__ W_hh)
{
    __shared__ __align__(16) __half hS[2][8 * HSTRIDE];
    __shared__ u16 tokS[8][SEQ];

    const int tid  = threadIdx.x;
    const int lane = tid & 31;
    const int w    = tid >> 5;          // warp 0..7
    const int g    = lane >> 2;         // 0..7
    const int t4   = lane & 3;          // 0..3
    const int b0   = blockIdx.x * 8;

    const int u  = 8 * w + g;           // hidden unit owned by this lane
    const int bA = 2 * t4;              // lane's two batches
    const int bB = bA + 1;

    // stationary A-fragments. tile0: rows g->i(u), g+8->f(u). tile1: g/o.
    u32 A0[4][4], A1[4][4];
#pragma unroll
    for (int K = 0; K < 4; K++) {
        const int c = 16 * K + 2 * t4;
        A0[K][0] = w_half2(W_hh,       u, c);      // i
        A0[K][1] = w_half2(W_hh,  64 + u, c);      // f
        A0[K][2] = w_half2(W_hh,       u, c + 8);
        A0[K][3] = w_half2(W_hh,  64 + u, c + 8);
        A1[K][0] = w_half2(W_hh, 128 + u, c);      // g
        A1[K][1] = w_half2(W_hh, 192 + u, c);      // o
        A1[K][2] = w_half2(W_hh, 128 + u, c + 8);
        A1[K][3] = w_half2(W_hh, 192 + u, c + 8);
    }

    // zero h buffers
    {
        __half* hz = &hS[0][0];
        for (int i = tid; i < 2 * 8 * HSTRIDE; i += 256) hz[i] = __float2half(0.0f);
    }
    // preload all tokens (u16)
    for (int i = tid; i < 8 * SEQ; i += 256) {
        const int b = i >> 9, t = i & (SEQ - 1);
        tokS[b][t] = (u16)__ldg(&x[(b0 + b) * SEQ + t]);
    }

    // gx(0): one uint2 (4 fp16) per (u, batch)
    uint2 gpA, gpB;
    {
        const int tokA = __ldg(&x[(b0 + bA) * SEQ]);
        const int tokB = __ldg(&x[(b0 + bB) * SEQ]);
        gpA = *reinterpret_cast<const uint2*>(g_emb_proj_h + (size_t)tokA * G4 + u * 4);
        gpB = *reinterpret_cast<const uint2*>(g_emb_proj_h + (size_t)tokB * G4 + u * 4);
    }

    float cA = 0.f, cB = 0.f, hAv = 0.f, hBv = 0.f;

    __syncthreads();

    for (int t = 0; t < SEQ; t++) {
        const int buf = t & 1;
        const __half* hb = hS[buf];

        // ---- gx prefetch for t+1 (8B each; L2-resident) ----
        const int tn = (t + 1 < SEQ) ? (t + 1) : (SEQ - 1);
        const int tokA = tokS[bA][tn];
        const int tokB = tokS[bB][tn];
        uint2 nA = *reinterpret_cast<const uint2*>(g_emb_proj_h + (size_t)tokA * G4 + u * 4);
        uint2 nB = *reinterpret_cast<const uint2*>(g_emb_proj_h + (size_t)tokB * G4 + u * 4);

        // ---- 8 HMMA, split-K (K0,K1 -> chain a; K2,K3 -> chain b) ----
        float d0a=0.f,d1a=0.f,d2a=0.f,d3a=0.f, d0b=0.f,d1b=0.f,d2b=0.f,d3b=0.f;
        float e0a=0.f,e1a=0.f,e2a=0.f,e3a=0.f, e0b=0.f,e1b=0.f,e2b=0.f,e3b=0.f;
#pragma unroll
        for (int K = 0; K < 4; K++) {
            const int kk = 16 * K + 2 * t4;
            u32 bb0 = *reinterpret_cast<const u32*>(&hb[g * HSTRIDE + kk]);
            u32 bb1 = *reinterpret_cast<const u32*>(&hb[g * HSTRIDE + kk + 8]);
            if (K < 2) {
                hmma16816(d0a,d1a,d2a,d3a, A0[K][0],A0[K][1],A0[K][2],A0[K][3], bb0,bb1);
                hmma16816(e0a,e1a,e2a,e3a, A1[K][0],A1[K][1],A1[K][2],A1[K][3], bb0,bb1);
            } else {
                hmma16816(d0b,d1b,d2b,d3b, A0[K][0],A0[K][1],A0[K][2],A0[K][3], bb0,bb1);
                hmma16816(e0b,e1b,e2b,e3b, A1[K][0],A1[K][1],A1[K][2],A1[K][3], bb0,bb1);
            }
        }

        // ---- epilogue: all lanes, register-local ----
        float giA, gfA, ggA, goA, giB, gfB, ggB, goB;
        gx4(gpA, giA, gfA, ggA, goA);
        gx4(gpB, giB, gfB, ggB, goB);

        float xi0 = d0a + d0b + giA, xi1 = d1a + d1b + giB;
        float xf0 = d2a + d2b + gfA, xf1 = d3a + d3b + gfB;
        float xg0 = e0a + e0b + ggA, xg1 = e1a + e1b + ggB;
        float xo0 = e2a + e2b + goA, xo1 = e3a + e3b + goB;

        u32 ti = h2tanh(pack_h2(0.5f * xi0, 0.5f * xi1));
        u32 tf = h2tanh(pack_h2(0.5f * xf0, 0.5f * xf1));
        u32 tg = h2tanh(pack_h2(xg0, xg1));
        u32 to = h2tanh(pack_h2(0.5f * xo0, 0.5f * xo1));
        half2 hti = *reinterpret_cast<half2*>(&ti);
        half2 htf = *reinterpret_cast<half2*>(&tf);
        half2 htg = *reinterpret_cast<half2*>(&tg);
        half2 hto = *reinterpret_cast<half2*>(&to);

        float i0 = fmaf(0.5f, __low2float(hti), 0.5f), i1 = fmaf(0.5f, __high2float(hti), 0.5f);
        float f0 = fmaf(0.5f, __low2float(htf), 0.5f), f1 = fmaf(0.5f, __high2float(htf), 0.5f);
        float g0 = __low2float(htg),                   g1 = __high2float(htg);
        float o0 = fmaf(0.5f, __low2float(hto), 0.5f), o1 = fmaf(0.5f, __high2float(hto), 0.5f);

        cA = fmaf(f0, cA, i0 * g0);
        cB = fmaf(f1, cB, i1 * g1);
        u32 tc = h2tanh(pack_h2(cA, cB));
        half2 htc = *reinterpret_cast<half2*>(&tc);
        hAv = o0 * __low2float(htc);
        hBv = o1 * __high2float(htc);

        // publish h(t+1)
        {
            __half* hn = hS[buf ^ 1];
            hn[bA * HSTRIDE + u] = __float2half(hAv);
            hn[bB * HSTRIDE + u] = __float2half(hBv);
        }
        gpA = nA; gpB = nB;

        __syncthreads();
    }

    g_hfin_h[(b0 + bA) * HID + u] = __float2half(hAv);
    g_hfin_h[(b0 + bB) * HID + u] = __float2half(hBv);
}

// ---------------------------------------------------------------------------
// K3: tensor-core FC, two-pass, chunk-split over grid.y (4 chunks per CTA).
// store=0: exp row-sums -> g_partial.  store=1: recompute, scale, store.
// (R14 version — measured best)
// ---------------------------------------------------------------------------
__global__ void __launch_bounds__(256) k3_fc(
    const float* __restrict__ W_fc, const float* __restrict__ b_fc,
    float* __restrict__ out, int store)
{
    __shared__ __align__(16) __half hs[64 * HSTRIDE];
    __shared__ float ws[8][64];
    __shared__ float riS[64];

    const int tid  = threadIdx.x;
    const int lane = tid & 31;
    const int w    = tid >> 5;
    const int g    = lane >> 2;
    const int t4   = lane & 3;

    const int cb   = blockIdx.x * 128;
    const int j1   = cb + 16 * w + g;
    const int j2   = j1 + 8;
    const bool v1  = (j1 < NUM_CITIES);
    const bool v2  = (j2 < NUM_CITIES);

    u32 A[4][4];
#pragma unroll
    for (int K = 0; K < 4; K++) {
        const int c = 16 * K + 2 * t4;
        A[K][0] = v1 ? w_half2(W_fc, j1, c)     : 0u;
        A[K][1] = v2 ? w_half2(W_fc, j2, c)     : 0u;
        A[K][2] = v1 ? w_half2(W_fc, j1, c + 8) : 0u;
        A[K][3] = v2 ? w_half2(W_fc, j2, c + 8) : 0u;
    }
    const float bias1 = v1 ? __ldg(&b_fc[j1]) : 0.0f;
    const float bias2 = v2 ? __ldg(&b_fc[j2]) : 0.0f;

    const u32* hsrc = reinterpret_cast<const u32*>(g_hfin_h);
    const int c0 = blockIdx.y * 4;       // 4 chunks per CTA

    for (int chunk = c0; chunk < c0 + 4; chunk++) {
        const int cb64 = chunk * 64;
        __syncthreads();
        for (int i = tid; i < 64 * 32; i += 256) {
            const int r = i >> 5;
            const int cp = i & 31;
            *reinterpret_cast<u32*>(&hs[r * HSTRIDE + 2 * cp]) =
                __ldg(&hsrc[(cb64 + r) * 32 + cp]);
        }
        if (store && tid < 64) riS[tid] = g_rowinv[cb64 + tid];
        __syncthreads();

#pragma unroll
        for (int nt = 0; nt < 8; nt++) {
            const int nb = cb64 + nt * 8;
            float d0 = 0.f, d1 = 0.f, d2 = 0.f, d3 = 0.f;
#pragma unroll
            for (int K = 0; K < 4; K++) {
                const int kk = 16 * K + 2 * t4;
                const __half* hrow = &hs[(nt * 8 + g) * HSTRIDE];
                u32 bb0 = *reinterpret_cast<const u32*>(&hrow[kk]);
                u32 bb1 = *reinterpret_cast<const u32*>(&hrow[kk + 8]);
                hmma16816(d0, d1, d2, d3, A[K][0], A[K][1], A[K][2], A[K][3], bb0, bb1);
            }
            const float LOG2E = 1.4426950408889634f;
            float e0 = v1 ? fast_ex2((d0 + bias1) * LOG2E) : 0.0f;
            float e1 = v1 ? fast_ex2((d1 + bias1) * LOG2E) : 0.0f;
            float e2 = v2 ? fast_ex2((d2 + bias2) * LOG2E) : 0.0f;
            float e3 = v2 ? fast_ex2((d3 + bias2) * LOG2E) : 0.0f;

            if (store) {
                const float r0v = riS[(nt * 8 + 2 * t4) & 63];
                const float r1v = riS[(nt * 8 + 2 * t4 + 1) & 63];
                const size_t rA = (size_t)(nb + 2 * t4) * NUM_CITIES;
                const size_t rB = (size_t)(nb + 2 * t4 + 1) * NUM_CITIES;
                if (v1) { __stcs(&out[rA + j1], e0 * r0v); __stcs(&out[rB + j1], e1 * r1v); }
                if (v2) { __stcs(&out[rA + j2], e2 * r0v); __stcs(&out[rB + j2], e3 * r1v); }
            } else {
                float s0 = e0 + e2;
                float s1 = e1 + e3;
#pragma unroll
                for (int m = 4; m <= 16; m <<= 1) {
                    s0 += __shfl_xor_sync(0xffffffffu, s0, m);
                    s1 += __shfl_xor_sync(0xffffffffu, s1, m);
                }
                if (g == 0) {
                    ws[w][nt * 8 + 2 * t4]     = s0;
                    ws[w][nt * 8 + 2 * t4 + 1] = s1;
                }
            }
        }
        if (!store) {
            __syncthreads();
            if (tid < 64) {
                float s = 0.0f;
#pragma unroll
                for (int ww = 0; ww < 8; ww++) s += ws[ww][tid];
                g_partial[blockIdx.x * BATCH + cb64 + tid] = s;
            }
        }
    }
}

// ---------------------------------------------------------------------------
// K3c: exact row-sum inverses. One warp per batch row.
// ---------------------------------------------------------------------------
__global__ void __launch_bounds__(128) k3c_inv()
{
    const int warp = (blockIdx.x * 128 + threadIdx.x) >> 5;
    const int lane = threadIdx.x & 31;
    float s = 0.0f;
    for (int cta = lane; cta < K3_CTAS; cta += 32)
        s += g_partial[cta * BATCH + warp];
    s += __shfl_xor_sync(0xffffffffu, s, 16);
    s += __shfl_xor_sync(0xffffffffu, s, 8);
    s += __shfl_xor_sync(0xffffffffu, s, 4);
    s += __shfl_xor_sync(0xffffffffu, s, 2);
    s += __shfl_xor_sync(0xffffffffu, s, 1);
    if (lane == 0) g_rowinv[warp] = 1.0f / s;
}

// ---------------------------------------------------------------------------
extern "C" void kernel_launch(void* const* d_in, const int* in_sizes, int n_in,
                              void* d_out, int out_size)
{
    (void)in_sizes; (void)n_in; (void)out_size;
    const int*   x    = (const int*)  d_in[0];
    const float* emb  = (const float*)d_in[1];
    const float* W_ih = (const float*)d_in[2];
    const float* W_hh = (const float*)d_in[3];
    const float* b_ih = (const float*)d_in[4];
    const float* b_hh = (const float*)d_in[5];
    const float* W_fc = (const float*)d_in[6];
    const float* b_fc = (const float*)d_in[7];
    float* out = (float*)d_out;

    k1_embproj<<<NUM_CITIES / 80, 256>>>(emb, W_ih, b_ih, b_hh);
    k_nop<<<1, 32>>>();
    k_nop<<<1, 32>>>();
    k2_lstm<<<BATCH / 8, 256>>>(x, W_hh);          // launch idx 3 -> profiled
    dim3 g3(K3_CTAS, 4);
    k3_fc<<<g3, 256>>>(W_fc, b_fc, out, 0);
    k3c_inv<<<256, 128>>>();
    k3_fc<<<g3, 256>>>(W_fc, b_fc, out, 1);
}